// round 9
// baseline (speedup 1.0000x reference)
#include <cuda_runtime.h>
#include <cuda_fp16.h>

#define NN   10000
#define EE   160000
#define BB   8
#define HH   64
#define PART 320            // 5 slots * 64 features per (node,batch) row
#define NB   (NN*BB)        // 80000
#define VHL  (NB*PART)      // one vh layer

// ---------------- device scratch ----------------
__device__ float g_deg_out[NN];
__device__ float g_deg_in[NN];
__device__ int   g_cnt[2][NN];
__device__ int   g_off[2][NN+1];
__device__ int   g_cur[2][NN];
__device__ int   g_nbr[2][EE];
__device__ float g_wgt[2][EE];

__device__ __half g_vx[VHL];      // x-part slots: 0=x 1=A_f x 2=A_r x 3=cheb_f 4=cheb_r
__device__ __half g_vh[2*VHL];    // h-part slots, per layer
__device__ __half g_vr[VHL];      // (R*h)-part slots
__device__ float  g_z [NB*HH];    // Z gate (fp32)
__device__ __half g_WZR[2*128*640];  // fp16 weights, n-major [l][n][640] for Z|R gemm
__device__ __half g_WH [2*64*640];   // fp16 weights, n-major [l][n][640] for H gemm

// ---------------- helpers ----------------
struct __align__(8)  h2x2 { __half2 a, b; };
struct __align__(16) h2x4 { __half2 a, b, c, d; };

__device__ __forceinline__ float sigm(float x) { return 1.f / (1.f + __expf(-x)); }

__device__ __forceinline__ void mma_f16(float &c0, float &c1, float &c2, float &c3,
                                        unsigned a0, unsigned a1, unsigned a2, unsigned a3,
                                        unsigned b0, unsigned b1) {
    asm volatile(
        "mma.sync.aligned.m16n8k16.row.col.f32.f16.f16.f32 "
        "{%0,%1,%2,%3}, {%4,%5,%6,%7}, {%8,%9}, {%0,%1,%2,%3};"
        : "+f"(c0), "+f"(c1), "+f"(c2), "+f"(c3)
        : "r"(a0), "r"(a1), "r"(a2), "r"(a3), "r"(b0), "r"(b1));
}

__device__ __forceinline__ __half* partbuf(int id, int l) {
    return id == 0 ? g_vx : (id == 1 ? g_vh + l * VHL : g_vr);
}

// ---------------- setup ----------------
__global__ void k_zero() {
    int i = blockIdx.x * 256 + threadIdx.x;
    if (i < NN) {
        g_deg_out[i] = 0.f; g_deg_in[i] = 0.f;
        g_cnt[0][i] = 0;    g_cnt[1][i] = 0;
    }
}

__global__ void k_degcnt(const float* __restrict__ ew, const int* __restrict__ ei) {
    int e = blockIdx.x * 256 + threadIdx.x;
    if (e >= EE) return;
    int s = ei[e], d = ei[EE + e];
    float w = ew[e];
    atomicAdd(&g_deg_out[s], w);
    atomicAdd(&g_deg_in[d],  w);
    atomicAdd(&g_cnt[0][d], 1);
    atomicAdd(&g_cnt[1][s], 1);
}

__global__ void k_scan() {   // grid=2, block=1024
    int d = blockIdx.x;
    __shared__ int sums[1024];
    int t = threadIdx.x;
    const int CH = 10;
    int base = t * CH;
    int s = 0;
    for (int i = 0; i < CH; i++) { int idx = base + i; if (idx < NN) s += g_cnt[d][idx]; }
    sums[t] = s; __syncthreads();
    for (int off = 1; off < 1024; off <<= 1) {
        int v = (t >= off) ? sums[t - off] : 0;
        __syncthreads();
        sums[t] += v;
        __syncthreads();
    }
    int run = (t == 0) ? 0 : sums[t - 1];
    for (int i = 0; i < CH; i++) {
        int idx = base + i;
        if (idx < NN) { g_off[d][idx] = run; g_cur[d][idx] = run; run += g_cnt[d][idx]; }
    }
    if (t == 1023) g_off[d][NN] = run;
}

__global__ void k_fill(const float* __restrict__ ew, const int* __restrict__ ei) {
    int e = blockIdx.x * 256 + threadIdx.x;
    if (e >= EE) return;
    int s = ei[e], d = ei[EE + e];
    float w = ew[e];
    float wo = g_deg_out[s]; float nout = w / (wo > 0.f ? wo : 1.f);
    float wi = g_deg_in[d];  float nin  = w / (wi > 0.f ? wi : 1.f);
    int p = atomicAdd(&g_cur[0][d], 1); g_nbr[0][p] = s; g_wgt[0][p] = nout;
    int q = atomicAdd(&g_cur[1][s], 1); g_nbr[1][q] = d; g_wgt[1][q] = nin;
}

__global__ void k_init_x(const float* __restrict__ go) {
    int t = blockIdx.x * 256 + threadIdx.x;
    if (t >= NB * HH) return;
    int f = t & 63; int rest = t >> 6;
    int n = rest % NN; int b = rest / NN;
    g_vx[(n * BB + b) * PART + f] = __float2half_rn(go[t]);
}

__global__ void k_load_h(const float* __restrict__ hs) {   // both layers
    int t = blockIdx.x * 256 + threadIdx.x;
    if (t >= 2 * NB * HH) return;
    int l = t >= NB * HH ? 1 : 0;
    int tt = t - l * NB * HH;
    int f = tt & 63; int rest = tt >> 6;
    int n = rest % NN; int b = rest / NN;
    g_vh[l * VHL + (n * BB + b) * PART + f] = __float2half_rn(hs[t]);
}

// W layout [L,2,K,128,64]. Slots: 0:(dir0+dir1,k0) 1:(0,k1) 2:(1,k1) 3:(0,k2) 4:(1,k2)
__device__ __forceinline__ float wslot(const float* W, int l, int s, int wrow, int o) {
    if (s == 0) {
        return W[((((l*2+0)*3+0)*128 + wrow)*64) + o] +
               W[((((l*2+1)*3+0)*128 + wrow)*64) + o];
    }
    int dir = (s == 1 || s == 3) ? 0 : 1;
    int k   = (s <= 2) ? 1 : 2;
    return W[((((l*2+dir)*3+k)*128 + wrow)*64) + o];
}

// builds fp16 n-major: g_WZR[l][n][j], j in [0,640)
__global__ void k_build_wzr(const float* __restrict__ Wz, const float* __restrict__ Wr) {
    int idx = blockIdx.x * 256 + threadIdx.x;
    if (idx >= 2 * 128 * 640) return;
    int l = idx >= 128 * 640 ? 1 : 0;
    int li = idx - l * 128 * 640;
    int n = li / 640, j = li % 640;
    int p = j / 320, s = (j % 320) / 64, f = j & 63;
    int wrow = p * 64 + f;
    const float* W = (n < 64) ? Wz : Wr;
    g_WZR[l * 128 * 640 + n * 640 + j] = __float2half_rn(wslot(W, l, s, wrow, n & 63));
}

__global__ void k_build_wh(const float* __restrict__ Wh) {
    int idx = blockIdx.x * 256 + threadIdx.x;
    if (idx >= 2 * 64 * 640) return;
    int l = idx >= 64 * 640 ? 1 : 0;
    int li = idx - l * 64 * 640;
    int n = li / 640, j = li % 640;
    int p = j / 320, s = (j % 320) / 64, f = j & 63;
    g_WH[l * 64 * 640 + n * 640 + j] = __float2half_rn(wslot(Wh, l, s, p * 64 + f, n));
}

// ---------------- propagation v4: 16B loads + unroll 8 ----------------
// grid: (NN/2, nbuf, 2 dirs); block 128 = 2 nodes; per node 64 thr = 8 batches x 8 lanes
__global__ void __launch_bounds__(128) k_prop4(int bufA, int bufB, int lvh,
                                               int s_in_f, int s_out_f,
                                               int s_in_r, int s_out_r,
                                               int cheb, int s_prev) {
    int dir = blockIdx.z;
    __half* buf = partbuf(blockIdx.y == 0 ? bufA : bufB, lvh);
    const int*   off = g_off[dir];
    const int*   nbr = g_nbr[dir];
    const float* wgt = g_wgt[dir];
    int s_in  = dir ? s_in_r  : s_in_f;
    int s_out = dir ? s_out_r : s_out_f;
    int n    = blockIdx.x * 2 + (threadIdx.x >> 6);
    int t    = threadIdx.x & 63;
    int b    = t >> 3;                 // batch 0..7
    int fo   = (t & 7) * 8;            // half offset within 64
    int beg = off[n], end = off[n + 1];
    int inoff = s_in * 64 + fo;
    float2 a0 = make_float2(0.f, 0.f), a1 = a0, a2 = a0, a3 = a0;
    int j = beg;
    int e8 = beg + ((end - beg) & ~7);
    for (; j < e8; j += 8) {
#pragma unroll
        for (int u = 0; u < 8; u++) {
            int   m  = __ldg(&nbr[j + u]);
            float ww = __ldg(&wgt[j + u]);
            h2x4 v = *(const h2x4*)(buf + (m * BB + b) * PART + inoff);
            float2 f;
            f = __half22float2(v.a); a0.x += ww * f.x; a0.y += ww * f.y;
            f = __half22float2(v.b); a1.x += ww * f.x; a1.y += ww * f.y;
            f = __half22float2(v.c); a2.x += ww * f.x; a2.y += ww * f.y;
            f = __half22float2(v.d); a3.x += ww * f.x; a3.y += ww * f.y;
        }
    }
    for (; j < end; j++) {
        int   m  = __ldg(&nbr[j]);
        float ww = __ldg(&wgt[j]);
        h2x4 v = *(const h2x4*)(buf + (m * BB + b) * PART + inoff);
        float2 f;
        f = __half22float2(v.a); a0.x += ww * f.x; a0.y += ww * f.y;
        f = __half22float2(v.b); a1.x += ww * f.x; a1.y += ww * f.y;
        f = __half22float2(v.c); a2.x += ww * f.x; a2.y += ww * f.y;
        f = __half22float2(v.d); a3.x += ww * f.x; a3.y += ww * f.y;
    }
    int orow = (n * BB + b) * PART;
    if (cheb) {
        h2x4 pv = *(const h2x4*)(buf + orow + s_prev * 64 + fo);
        float2 p;
        p = __half22float2(pv.a); a0.x = 2.f * a0.x - p.x; a0.y = 2.f * a0.y - p.y;
        p = __half22float2(pv.b); a1.x = 2.f * a1.x - p.x; a1.y = 2.f * a1.y - p.y;
        p = __half22float2(pv.c); a2.x = 2.f * a2.x - p.x; a2.y = 2.f * a2.y - p.y;
        p = __half22float2(pv.d); a3.x = 2.f * a3.x - p.x; a3.y = 2.f * a3.y - p.y;
    }
    h2x4 o;
    o.a = __floats2half2_rn(a0.x, a0.y);
    o.b = __floats2half2_rn(a1.x, a1.y);
    o.c = __floats2half2_rn(a2.x, a2.y);
    o.d = __floats2half2_rn(a3.x, a3.y);
    *(h2x4*)(buf + orow + s_out * 64 + fo) = o;
}

// ---------------- fp16 tensor-core GEMMs ----------------
// Z|R: [80000 x 640] @ [640 x 128]; A row = (vx row | vh row), all fp16
// Block 256 = 8 warps, tile 128x128, warps 4x2 (32 rows x 64 cols each)
__global__ void __launch_bounds__(256) k_gemm_zr(int l,
                                                 const float* __restrict__ bz,
                                                 const float* __restrict__ br) {
    __shared__ __half As[128][40];   // row-major, padded (conflict-free quad reads)
    __shared__ __half Bs[128][40];   // n-major: Bs[n][k]
    const __half* W = g_WZR + l * 128 * 640;
    const __half* vh = g_vh + l * VHL;
    int tid = threadIdx.x;
    int wid = tid >> 5, lane = tid & 31;
    int warpM = wid & 3, warpN = wid >> 2;
    int g4 = lane >> 2, t4 = lane & 3;
    int rowBase = blockIdx.x * 128;

    float c[2][8][4];
#pragma unroll
    for (int mt = 0; mt < 2; mt++)
#pragma unroll
        for (int nt = 0; nt < 8; nt++)
#pragma unroll
            for (int i = 0; i < 4; i++) c[mt][nt][i] = 0.f;

    for (int kk = 0; kk < 20; kk++) {
        const __half* Asrc = (kk < 10) ? g_vx : vh;
        int soff = (kk < 10 ? kk : kk - 10) * 32;
#pragma unroll
        for (int t = 0; t < 2; t++) {           // A: 128x32 halves = 512 h2x4
            int id = tid + t * 256;
            int r = id >> 2, c8 = (id & 3) * 8;
            *(h2x4*)&As[r][c8] = *(const h2x4*)(Asrc + (rowBase + r) * PART + soff + c8);
        }
#pragma unroll
        for (int t = 0; t < 2; t++) {           // B: 128 n x 32 k halves = 512 h2x4
            int id = tid + t * 256;
            int n = id >> 2, c8 = (id & 3) * 8;
            *(h2x4*)&Bs[n][c8] = *(const h2x4*)(W + n * 640 + kk * 32 + c8);
        }
        __syncthreads();
#pragma unroll
        for (int kc = 0; kc < 2; kc++) {
            int k0 = kc * 16;
            int kA = k0 + 2 * t4;
            unsigned a[2][4];
#pragma unroll
            for (int mt = 0; mt < 2; mt++) {
                int rm = warpM * 32 + mt * 16;
                a[mt][0] = *(const unsigned*)&As[rm + g4][kA];
                a[mt][1] = *(const unsigned*)&As[rm + g4 + 8][kA];
                a[mt][2] = *(const unsigned*)&As[rm + g4][kA + 8];
                a[mt][3] = *(const unsigned*)&As[rm + g4 + 8][kA + 8];
            }
#pragma unroll
            for (int nt = 0; nt < 8; nt++) {
                int cn = warpN * 64 + nt * 8;
                unsigned b0 = *(const unsigned*)&Bs[cn + g4][kA];
                unsigned b1 = *(const unsigned*)&Bs[cn + g4][kA + 8];
#pragma unroll
                for (int mt = 0; mt < 2; mt++)
                    mma_f16(c[mt][nt][0], c[mt][nt][1], c[mt][nt][2], c[mt][nt][3],
                            a[mt][0], a[mt][1], a[mt][2], a[mt][3], b0, b1);
            }
        }
        __syncthreads();
    }

    // epilogue: warpN==0 -> Z gate; warpN==1 -> R gate * h
#pragma unroll
    for (int mt = 0; mt < 2; mt++) {
#pragma unroll
        for (int nt = 0; nt < 8; nt++) {
            int gr0 = rowBase + warpM * 32 + mt * 16 + g4;
            int cv  = nt * 8 + 2 * t4;
            if (warpN == 0) {
                float bz0 = __ldg(&bz[cv]), bz1 = __ldg(&bz[cv + 1]);
                g_z[gr0 * HH + cv]           = sigm(c[mt][nt][0] + bz0);
                g_z[gr0 * HH + cv + 1]       = sigm(c[mt][nt][1] + bz1);
                g_z[(gr0 + 8) * HH + cv]     = sigm(c[mt][nt][2] + bz0);
                g_z[(gr0 + 8) * HH + cv + 1] = sigm(c[mt][nt][3] + bz1);
            } else {
                float br0 = __ldg(&br[cv]), br1 = __ldg(&br[cv + 1]);
                float h00 = __half2float(vh[gr0 * PART + cv]);
                float h01 = __half2float(vh[gr0 * PART + cv + 1]);
                float h10 = __half2float(vh[(gr0 + 8) * PART + cv]);
                float h11 = __half2float(vh[(gr0 + 8) * PART + cv + 1]);
                g_vr[gr0 * PART + cv]           = __float2half_rn(sigm(c[mt][nt][0] + br0) * h00);
                g_vr[gr0 * PART + cv + 1]       = __float2half_rn(sigm(c[mt][nt][1] + br1) * h01);
                g_vr[(gr0 + 8) * PART + cv]     = __float2half_rn(sigm(c[mt][nt][2] + br0) * h10);
                g_vr[(gr0 + 8) * PART + cv + 1] = __float2half_rn(sigm(c[mt][nt][3] + br1) * h11);
            }
        }
    }
}

// H: [80000 x 640] @ [640 x 64]; A row = (vx row | vr row). GRU update -> vx slot0
// Block 256 = 8 warps, tile 128x64, each warp 16 rows x 64 cols
__global__ void __launch_bounds__(256) k_gemm_h(int l, const float* __restrict__ bh) {
    __shared__ __half As[128][40];
    __shared__ __half Bs[64][40];
    const __half* W = g_WH + l * 64 * 640;
    const __half* vh = g_vh + l * VHL;
    int tid = threadIdx.x;
    int wid = tid >> 5, lane = tid & 31;
    int g4 = lane >> 2, t4 = lane & 3;
    int rowBase = blockIdx.x * 128;

    float c[8][4];
#pragma unroll
    for (int nt = 0; nt < 8; nt++)
#pragma unroll
        for (int i = 0; i < 4; i++) c[nt][i] = 0.f;

    for (int kk = 0; kk < 20; kk++) {
        const __half* Asrc = (kk < 10) ? g_vx : g_vr;
        int soff = (kk < 10 ? kk : kk - 10) * 32;
#pragma unroll
        for (int t = 0; t < 2; t++) {           // A: 512 h2x4
            int id = tid + t * 256;
            int r = id >> 2, c8 = (id & 3) * 8;
            *(h2x4*)&As[r][c8] = *(const h2x4*)(Asrc + (rowBase + r) * PART + soff + c8);
        }
        {                                       // B: 64 n x 32 k = 256 h2x4
            int n = tid >> 2, c8 = (tid & 3) * 8;
            *(h2x4*)&Bs[n][c8] = *(const h2x4*)(W + n * 640 + kk * 32 + c8);
        }
        __syncthreads();
#pragma unroll
        for (int kc = 0; kc < 2; kc++) {
            int kA = kc * 16 + 2 * t4;
            int rm = wid * 16;
            unsigned a0 = *(const unsigned*)&As[rm + g4][kA];
            unsigned a1 = *(const unsigned*)&As[rm + g4 + 8][kA];
            unsigned a2 = *(const unsigned*)&As[rm + g4][kA + 8];
            unsigned a3 = *(const unsigned*)&As[rm + g4 + 8][kA + 8];
#pragma unroll
            for (int nt = 0; nt < 8; nt++) {
                unsigned b0 = *(const unsigned*)&Bs[nt * 8 + g4][kA];
                unsigned b1 = *(const unsigned*)&Bs[nt * 8 + g4][kA + 8];
                mma_f16(c[nt][0], c[nt][1], c[nt][2], c[nt][3], a0, a1, a2, a3, b0, b1);
            }
        }
        __syncthreads();
    }

    // epilogue: GRU update, write new h into vx slot0 (fp16)
#pragma unroll
    for (int nt = 0; nt < 8; nt++) {
        int gr0 = rowBase + wid * 16 + g4;
        int cv  = nt * 8 + 2 * t4;
        float bh0 = __ldg(&bh[cv]), bh1 = __ldg(&bh[cv + 1]);
#pragma unroll
        for (int half_i = 0; half_i < 2; half_i++) {
            int gr = gr0 + half_i * 8;
            float ht0 = tanhf(c[nt][half_i * 2 + 0] + bh0);
            float ht1 = tanhf(c[nt][half_i * 2 + 1] + bh1);
            float z0 = g_z[gr * HH + cv], z1 = g_z[gr * HH + cv + 1];
            float h0 = __half2float(vh[gr * PART + cv]);
            float h1 = __half2float(vh[gr * PART + cv + 1]);
            g_vx[gr * PART + cv]     = __float2half_rn(z0 * h0 + (1.f - z0) * ht0);
            g_vx[gr * PART + cv + 1] = __float2half_rn(z1 * h1 + (1.f - z1) * ht1);
        }
    }
}

// ---------------- projection ----------------
__global__ void __launch_bounds__(256) k_proj(const float* __restrict__ pw,
                                              const float* __restrict__ pb,
                                              float* __restrict__ out) {
    __shared__ float Ws[64 * 32];
    __shared__ float Bsh[32];
    int tid = threadIdx.x;
    for (int i = tid; i < 64 * 32; i += 256) Ws[i] = pw[i];
    if (tid < 32) Bsh[tid] = pb[tid];
    __syncthreads();
    int w = tid >> 5, lane = tid & 31;
    int g = blockIdx.x * 8 + w;
    const __half* x = g_vx + g * PART;
    float xv0 = __half2float(x[lane]);
    float xv1 = __half2float(x[32 + lane]);
    float acc = Bsh[lane];
#pragma unroll
    for (int f = 0; f < 32; f++)
        acc += __shfl_sync(0xffffffffu, xv0, f) * Ws[f * 32 + lane];
#pragma unroll
    for (int f = 0; f < 32; f++)
        acc += __shfl_sync(0xffffffffu, xv1, f) * Ws[(32 + f) * 32 + lane];
    int n = g >> 3, b = g & 7;
    out[(b * NN + n) * 32 + lane] = acc;
}

// ---------------- launch ----------------
extern "C" void kernel_launch(void* const* d_in, const int* in_sizes, int n_in,
                              void* d_out, int out_size) {
    (void)in_sizes; (void)n_in; (void)out_size;
    const float* ew = (const float*)d_in[0];
    const float* hs = (const float*)d_in[1];
    const float* go = (const float*)d_in[2];
    const float* Wz = (const float*)d_in[3];
    const float* bz = (const float*)d_in[4];
    const float* Wr = (const float*)d_in[5];
    const float* br = (const float*)d_in[6];
    const float* Wh = (const float*)d_in[7];
    const float* bh = (const float*)d_in[8];
    const float* pw = (const float*)d_in[9];
    const float* pb = (const float*)d_in[10];
    const int*   ei = (const int*)d_in[11];
    float* out = (float*)d_out;

    k_zero  <<<(NN + 255) / 256, 256>>>();
    k_degcnt<<<(EE + 255) / 256, 256>>>(ew, ei);
    k_scan  <<<2, 1024>>>();
    k_fill  <<<(EE + 255) / 256, 256>>>(ew, ei);
    k_init_x<<<(NB * HH + 255) / 256, 256>>>(go);
    k_load_h<<<(2 * NB * HH + 255) / 256, 256>>>(hs);
    k_build_wzr<<<(2 * 128 * 640 + 255) / 256, 256>>>(Wz, Wr);
    k_build_wh <<<(2 * 64 * 640 + 255) / 256, 256>>>(Wh);

    dim3 g2(NN / 2, 2, 2), g1(NN / 2, 1, 2);
    for (int l = 0; l < 2; l++) {
        k_prop4<<<g2, 128>>>(0, 1, l, 0, 1, 0, 2, 0, 0);   // slot1 = A_f s0; slot2 = A_r s0
        k_prop4<<<g2, 128>>>(0, 1, l, 1, 3, 2, 4, 1, 0);   // slot3/4 = 2 A(slot1/2) - s0

        k_gemm_zr<<<625, 256>>>(l, bz + l * HH, br + l * HH);

        k_prop4<<<g1, 128>>>(2, 2, l, 0, 1, 0, 2, 0, 0);
        k_prop4<<<g1, 128>>>(2, 2, l, 1, 3, 2, 4, 1, 0);

        k_gemm_h<<<625, 256>>>(l, bh + l * HH);            // -> new h in vx slot0
    }

    k_proj<<<NB / 8, 256>>>(pw, pb, out);
}

// round 11
// speedup vs baseline: 1.0156x; 1.0156x over previous
#include <cuda_runtime.h>
#include <cuda_fp16.h>

#define NN   10000
#define EE   160000
#define BB   8
#define HH   64
#define PART 320            // 5 slots * 64 features per (node,batch) row
#define NB   (NN*BB)        // 80000
#define VHL  (NB*PART)      // one vh layer

// ---------------- device scratch ----------------
__device__ float g_deg_out[NN];
__device__ float g_deg_in[NN];
__device__ int   g_cnt[2][NN];
__device__ int   g_off[2][NN+1];
__device__ int   g_cur[2][NN];
__device__ int   g_nbr[2][EE];
__device__ float g_wgt[2][EE];

__device__ __half g_vx[VHL];      // x-part slots: 0=x 1=A_f x 2=A_r x 3=cheb_f 4=cheb_r
__device__ __half g_vh[2*VHL];    // h-part slots, per layer
__device__ __half g_vr[VHL];      // (R*h)-part slots
__device__ float  g_z [NB*HH];    // Z gate (fp32)
__device__ __half g_WZR[2*128*640];  // fp16 weights, n-major [l][n][640] for Z|R gemm
__device__ __half g_WH [2*64*640];   // fp16 weights, n-major [l][n][640] for H gemm

// ---------------- helpers ----------------
struct __align__(8)  h2x2 { __half2 a, b; };
struct __align__(16) h2x4 { __half2 a, b, c, d; };

__device__ __forceinline__ float sigm(float x) { return 1.f / (1.f + __expf(-x)); }

__device__ __forceinline__ void mma_f16(float &c0, float &c1, float &c2, float &c3,
                                        unsigned a0, unsigned a1, unsigned a2, unsigned a3,
                                        unsigned b0, unsigned b1) {
    asm volatile(
        "mma.sync.aligned.m16n8k16.row.col.f32.f16.f16.f32 "
        "{%0,%1,%2,%3}, {%4,%5,%6,%7}, {%8,%9}, {%0,%1,%2,%3};"
        : "+f"(c0), "+f"(c1), "+f"(c2), "+f"(c3)
        : "r"(a0), "r"(a1), "r"(a2), "r"(a3), "r"(b0), "r"(b1));
}

__device__ __forceinline__ __half* partbuf(int id, int l) {
    return id == 0 ? g_vx : (id == 1 ? g_vh + l * VHL : g_vr);
}

// ---------------- setup ----------------
__global__ void k_zero() {
    int i = blockIdx.x * 256 + threadIdx.x;
    if (i < NN) {
        g_deg_out[i] = 0.f; g_deg_in[i] = 0.f;
        g_cnt[0][i] = 0;    g_cnt[1][i] = 0;
    }
}

__global__ void k_degcnt(const float* __restrict__ ew, const int* __restrict__ ei) {
    int e = blockIdx.x * 256 + threadIdx.x;
    if (e >= EE) return;
    int s = ei[e], d = ei[EE + e];
    float w = ew[e];
    atomicAdd(&g_deg_out[s], w);
    atomicAdd(&g_deg_in[d],  w);
    atomicAdd(&g_cnt[0][d], 1);
    atomicAdd(&g_cnt[1][s], 1);
}

__global__ void k_scan() {   // grid=2, block=1024
    int d = blockIdx.x;
    __shared__ int sums[1024];
    int t = threadIdx.x;
    const int CH = 10;
    int base = t * CH;
    int s = 0;
    for (int i = 0; i < CH; i++) { int idx = base + i; if (idx < NN) s += g_cnt[d][idx]; }
    sums[t] = s; __syncthreads();
    for (int off = 1; off < 1024; off <<= 1) {
        int v = (t >= off) ? sums[t - off] : 0;
        __syncthreads();
        sums[t] += v;
        __syncthreads();
    }
    int run = (t == 0) ? 0 : sums[t - 1];
    for (int i = 0; i < CH; i++) {
        int idx = base + i;
        if (idx < NN) { g_off[d][idx] = run; g_cur[d][idx] = run; run += g_cnt[d][idx]; }
    }
    if (t == 1023) g_off[d][NN] = run;
}

__global__ void k_fill(const float* __restrict__ ew, const int* __restrict__ ei) {
    int e = blockIdx.x * 256 + threadIdx.x;
    if (e >= EE) return;
    int s = ei[e], d = ei[EE + e];
    float w = ew[e];
    float wo = g_deg_out[s]; float nout = w / (wo > 0.f ? wo : 1.f);
    float wi = g_deg_in[d];  float nin  = w / (wi > 0.f ? wi : 1.f);
    int p = atomicAdd(&g_cur[0][d], 1); g_nbr[0][p] = s; g_wgt[0][p] = nout;
    int q = atomicAdd(&g_cur[1][s], 1); g_nbr[1][q] = d; g_wgt[1][q] = nin;
}

__global__ void k_init_x(const float* __restrict__ go) {
    int t = blockIdx.x * 256 + threadIdx.x;
    if (t >= NB * HH) return;
    int f = t & 63; int rest = t >> 6;
    int n = rest % NN; int b = rest / NN;
    g_vx[(n * BB + b) * PART + f] = __float2half_rn(go[t]);
}

__global__ void k_load_h(const float* __restrict__ hs) {   // both layers
    int t = blockIdx.x * 256 + threadIdx.x;
    if (t >= 2 * NB * HH) return;
    int l = t >= NB * HH ? 1 : 0;
    int tt = t - l * NB * HH;
    int f = tt & 63; int rest = tt >> 6;
    int n = rest % NN; int b = rest / NN;
    g_vh[l * VHL + (n * BB + b) * PART + f] = __float2half_rn(hs[t]);
}

// W layout [L,2,K,128,64]. Slots: 0:(dir0+dir1,k0) 1:(0,k1) 2:(1,k1) 3:(0,k2) 4:(1,k2)
__device__ __forceinline__ float wslot(const float* W, int l, int s, int wrow, int o) {
    if (s == 0) {
        return W[((((l*2+0)*3+0)*128 + wrow)*64) + o] +
               W[((((l*2+1)*3+0)*128 + wrow)*64) + o];
    }
    int dir = (s == 1 || s == 3) ? 0 : 1;
    int k   = (s <= 2) ? 1 : 2;
    return W[((((l*2+dir)*3+k)*128 + wrow)*64) + o];
}

// builds fp16 n-major: g_WZR[l][n][j], j in [0,640)
__global__ void k_build_wzr(const float* __restrict__ Wz, const float* __restrict__ Wr) {
    int idx = blockIdx.x * 256 + threadIdx.x;
    if (idx >= 2 * 128 * 640) return;
    int l = idx >= 128 * 640 ? 1 : 0;
    int li = idx - l * 128 * 640;
    int n = li / 640, j = li % 640;
    int p = j / 320, s = (j % 320) / 64, f = j & 63;
    int wrow = p * 64 + f;
    const float* W = (n < 64) ? Wz : Wr;
    g_WZR[l * 128 * 640 + n * 640 + j] = __float2half_rn(wslot(W, l, s, wrow, n & 63));
}

__global__ void k_build_wh(const float* __restrict__ Wh) {
    int idx = blockIdx.x * 256 + threadIdx.x;
    if (idx >= 2 * 64 * 640) return;
    int l = idx >= 64 * 640 ? 1 : 0;
    int li = idx - l * 64 * 640;
    int n = li / 640, j = li % 640;
    int p = j / 320, s = (j % 320) / 64, f = j & 63;
    g_WH[l * 64 * 640 + n * 640 + j] = __float2half_rn(wslot(Wh, l, s, p * 64 + f, n));
}

// ---------------- propagation v5: R7 load shape + in-block edge split ----------------
// grid: (NN, nbuf, 2 dirs); block 256 = 2 edge-groups x (4 warps: 2 batches x 16 lanes x 4 halves)
__global__ void __launch_bounds__(256) k_prop5(int bufA, int bufB, int lvh,
                                               int s_in_f, int s_out_f,
                                               int s_in_r, int s_out_r,
                                               int cheb, int s_prev) {
    __shared__ float4 sred[128];
    int dir = blockIdx.z;
    __half* buf = partbuf(blockIdx.y == 0 ? bufA : bufB, lvh);
    const int*   off = g_off[dir];
    const int*   nbr = g_nbr[dir];
    const float* wgt = g_wgt[dir];
    int s_in  = dir ? s_in_r  : s_in_f;
    int s_out = dir ? s_out_r : s_out_f;
    int n    = blockIdx.x;
    int grp  = threadIdx.x >> 7;       // edge group 0/1
    int t    = threadIdx.x & 127;
    int w    = t >> 5;
    int lane = t & 31;
    int b    = w * 2 + (lane >> 4);
    int fo   = (lane & 15) * 4;        // half offset within 64
    int beg = off[n], end = off[n + 1];
    int mid = beg + ((end - beg) >> 1);
    int jb = grp ? mid : beg;
    int je = grp ? end : mid;
    int inoff = s_in * 64 + fo;
    float4 acc = make_float4(0.f, 0.f, 0.f, 0.f);
    int j = jb;
    int e8 = jb + ((je - jb) & ~7);
    for (; j < e8; j += 8) {
#pragma unroll
        for (int u = 0; u < 8; u++) {
            int   m  = __ldg(&nbr[j + u]);
            float ww = __ldg(&wgt[j + u]);
            h2x2 v = *(const h2x2*)(buf + (m * BB + b) * PART + inoff);
            float2 f01 = __half22float2(v.a);
            float2 f23 = __half22float2(v.b);
            acc.x += ww * f01.x; acc.y += ww * f01.y;
            acc.z += ww * f23.x; acc.w += ww * f23.y;
        }
    }
    for (; j < je; j++) {
        int   m  = __ldg(&nbr[j]);
        float ww = __ldg(&wgt[j]);
        h2x2 v = *(const h2x2*)(buf + (m * BB + b) * PART + inoff);
        float2 f01 = __half22float2(v.a);
        float2 f23 = __half22float2(v.b);
        acc.x += ww * f01.x; acc.y += ww * f01.y;
        acc.z += ww * f23.x; acc.w += ww * f23.y;
    }
    int sidx = b * 16 + (lane & 15);
    if (grp) sred[sidx] = acc;
    __syncthreads();
    if (!grp) {
        float4 p2 = sred[sidx];
        acc.x += p2.x; acc.y += p2.y; acc.z += p2.z; acc.w += p2.w;
        int orow = (n * BB + b) * PART;
        float4 res = acc;
        if (cheb) {
            h2x2 pv = *(const h2x2*)(buf + orow + s_prev * 64 + fo);
            float2 p01 = __half22float2(pv.a);
            float2 p23 = __half22float2(pv.b);
            res.x = 2.f * acc.x - p01.x; res.y = 2.f * acc.y - p01.y;
            res.z = 2.f * acc.z - p23.x; res.w = 2.f * acc.w - p23.y;
        }
        h2x2 o;
        o.a = __floats2half2_rn(res.x, res.y);
        o.b = __floats2half2_rn(res.z, res.w);
        *(h2x2*)(buf + orow + s_out * 64 + fo) = o;
    }
}

// ---------------- fp16 tensor-core GEMMs ----------------
// Z|R: [80000 x 640] @ [640 x 128]; A row = (vx row | vh row), all fp16
// Block 256 = 8 warps, tile 128x128, warps 4x2 (32 rows x 64 cols each)
__global__ void __launch_bounds__(256) k_gemm_zr(int l,
                                                 const float* __restrict__ bz,
                                                 const float* __restrict__ br) {
    __shared__ __half As[128][40];   // row-major, padded (conflict-free quad reads)
    __shared__ __half Bs[128][40];   // n-major: Bs[n][k]
    const __half* W = g_WZR + l * 128 * 640;
    const __half* vh = g_vh + l * VHL;
    int tid = threadIdx.x;
    int wid = tid >> 5, lane = tid & 31;
    int warpM = wid & 3, warpN = wid >> 2;
    int g4 = lane >> 2, t4 = lane & 3;
    int rowBase = blockIdx.x * 128;

    float c[2][8][4];
#pragma unroll
    for (int mt = 0; mt < 2; mt++)
#pragma unroll
        for (int nt = 0; nt < 8; nt++)
#pragma unroll
            for (int i = 0; i < 4; i++) c[mt][nt][i] = 0.f;

    for (int kk = 0; kk < 20; kk++) {
        const __half* Asrc = (kk < 10) ? g_vx : vh;
        int soff = (kk < 10 ? kk : kk - 10) * 32;
#pragma unroll
        for (int t = 0; t < 2; t++) {           // A: 128x32 halves = 512 h2x4
            int id = tid + t * 256;
            int r = id >> 2, c8 = (id & 3) * 8;
            *(h2x4*)&As[r][c8] = *(const h2x4*)(Asrc + (rowBase + r) * PART + soff + c8);
        }
#pragma unroll
        for (int t = 0; t < 2; t++) {           // B: 128 n x 32 k halves = 512 h2x4
            int id = tid + t * 256;
            int n = id >> 2, c8 = (id & 3) * 8;
            *(h2x4*)&Bs[n][c8] = *(const h2x4*)(W + n * 640 + kk * 32 + c8);
        }
        __syncthreads();
#pragma unroll
        for (int kc = 0; kc < 2; kc++) {
            int k0 = kc * 16;
            int kA = k0 + 2 * t4;
            unsigned a[2][4];
#pragma unroll
            for (int mt = 0; mt < 2; mt++) {
                int rm = warpM * 32 + mt * 16;
                a[mt][0] = *(const unsigned*)&As[rm + g4][kA];
                a[mt][1] = *(const unsigned*)&As[rm + g4 + 8][kA];
                a[mt][2] = *(const unsigned*)&As[rm + g4][kA + 8];
                a[mt][3] = *(const unsigned*)&As[rm + g4 + 8][kA + 8];
            }
#pragma unroll
            for (int nt = 0; nt < 8; nt++) {
                int cn = warpN * 64 + nt * 8;
                unsigned b0 = *(const unsigned*)&Bs[cn + g4][kA];
                unsigned b1 = *(const unsigned*)&Bs[cn + g4][kA + 8];
#pragma unroll
                for (int mt = 0; mt < 2; mt++)
                    mma_f16(c[mt][nt][0], c[mt][nt][1], c[mt][nt][2], c[mt][nt][3],
                            a[mt][0], a[mt][1], a[mt][2], a[mt][3], b0, b1);
            }
        }
        __syncthreads();
    }

    // epilogue: warpN==0 -> Z gate; warpN==1 -> R gate * h
#pragma unroll
    for (int mt = 0; mt < 2; mt++) {
#pragma unroll
        for (int nt = 0; nt < 8; nt++) {
            int gr0 = rowBase + warpM * 32 + mt * 16 + g4;
            int cv  = nt * 8 + 2 * t4;
            if (warpN == 0) {
                float bz0 = __ldg(&bz[cv]), bz1 = __ldg(&bz[cv + 1]);
                g_z[gr0 * HH + cv]           = sigm(c[mt][nt][0] + bz0);
                g_z[gr0 * HH + cv + 1]       = sigm(c[mt][nt][1] + bz1);
                g_z[(gr0 + 8) * HH + cv]     = sigm(c[mt][nt][2] + bz0);
                g_z[(gr0 + 8) * HH + cv + 1] = sigm(c[mt][nt][3] + bz1);
            } else {
                float br0 = __ldg(&br[cv]), br1 = __ldg(&br[cv + 1]);
                float h00 = __half2float(vh[gr0 * PART + cv]);
                float h01 = __half2float(vh[gr0 * PART + cv + 1]);
                float h10 = __half2float(vh[(gr0 + 8) * PART + cv]);
                float h11 = __half2float(vh[(gr0 + 8) * PART + cv + 1]);
                g_vr[gr0 * PART + cv]           = __float2half_rn(sigm(c[mt][nt][0] + br0) * h00);
                g_vr[gr0 * PART + cv + 1]       = __float2half_rn(sigm(c[mt][nt][1] + br1) * h01);
                g_vr[(gr0 + 8) * PART + cv]     = __float2half_rn(sigm(c[mt][nt][2] + br0) * h10);
                g_vr[(gr0 + 8) * PART + cv + 1] = __float2half_rn(sigm(c[mt][nt][3] + br1) * h11);
            }
        }
    }
}

// H: [80000 x 640] @ [640 x 64]; A row = (vx row | vr row). GRU update -> vx slot0
// Block 256 = 8 warps, tile 128x64, each warp 16 rows x 64 cols
__global__ void __launch_bounds__(256) k_gemm_h(int l, const float* __restrict__ bh) {
    __shared__ __half As[128][40];
    __shared__ __half Bs[64][40];
    const __half* W = g_WH + l * 64 * 640;
    const __half* vh = g_vh + l * VHL;
    int tid = threadIdx.x;
    int wid = tid >> 5, lane = tid & 31;
    int g4 = lane >> 2, t4 = lane & 3;
    int rowBase = blockIdx.x * 128;

    float c[8][4];
#pragma unroll
    for (int nt = 0; nt < 8; nt++)
#pragma unroll
        for (int i = 0; i < 4; i++) c[nt][i] = 0.f;

    for (int kk = 0; kk < 20; kk++) {
        const __half* Asrc = (kk < 10) ? g_vx : g_vr;
        int soff = (kk < 10 ? kk : kk - 10) * 32;
#pragma unroll
        for (int t = 0; t < 2; t++) {           // A: 512 h2x4
            int id = tid + t * 256;
            int r = id >> 2, c8 = (id & 3) * 8;
            *(h2x4*)&As[r][c8] = *(const h2x4*)(Asrc + (rowBase + r) * PART + soff + c8);
        }
        {                                       // B: 64 n x 32 k = 256 h2x4
            int n = tid >> 2, c8 = (tid & 3) * 8;
            *(h2x4*)&Bs[n][c8] = *(const h2x4*)(W + n * 640 + kk * 32 + c8);
        }
        __syncthreads();
#pragma unroll
        for (int kc = 0; kc < 2; kc++) {
            int kA = kc * 16 + 2 * t4;
            int rm = wid * 16;
            unsigned a0 = *(const unsigned*)&As[rm + g4][kA];
            unsigned a1 = *(const unsigned*)&As[rm + g4 + 8][kA];
            unsigned a2 = *(const unsigned*)&As[rm + g4][kA + 8];
            unsigned a3 = *(const unsigned*)&As[rm + g4 + 8][kA + 8];
#pragma unroll
            for (int nt = 0; nt < 8; nt++) {
                unsigned b0 = *(const unsigned*)&Bs[nt * 8 + g4][kA];
                unsigned b1 = *(const unsigned*)&Bs[nt * 8 + g4][kA + 8];
                mma_f16(c[nt][0], c[nt][1], c[nt][2], c[nt][3], a0, a1, a2, a3, b0, b1);
            }
        }
        __syncthreads();
    }

    // epilogue: GRU update, write new h into vx slot0 (fp16)
#pragma unroll
    for (int nt = 0; nt < 8; nt++) {
        int gr0 = rowBase + wid * 16 + g4;
        int cv  = nt * 8 + 2 * t4;
        float bh0 = __ldg(&bh[cv]), bh1 = __ldg(&bh[cv + 1]);
#pragma unroll
        for (int half_i = 0; half_i < 2; half_i++) {
            int gr = gr0 + half_i * 8;
            float ht0 = tanhf(c[nt][half_i * 2 + 0] + bh0);
            float ht1 = tanhf(c[nt][half_i * 2 + 1] + bh1);
            float z0 = g_z[gr * HH + cv], z1 = g_z[gr * HH + cv + 1];
            float h0 = __half2float(vh[gr * PART + cv]);
            float h1 = __half2float(vh[gr * PART + cv + 1]);
            g_vx[gr * PART + cv]     = __float2half_rn(z0 * h0 + (1.f - z0) * ht0);
            g_vx[gr * PART + cv + 1] = __float2half_rn(z1 * h1 + (1.f - z1) * ht1);
        }
    }
}

// ---------------- projection ----------------
__global__ void __launch_bounds__(256) k_proj(const float* __restrict__ pw,
                                              const float* __restrict__ pb,
                                              float* __restrict__ out) {
    __shared__ float Ws[64 * 32];
    __shared__ float Bsh[32];
    int tid = threadIdx.x;
    for (int i = tid; i < 64 * 32; i += 256) Ws[i] = pw[i];
    if (tid < 32) Bsh[tid] = pb[tid];
    __syncthreads();
    int w = tid >> 5, lane = tid & 31;
    int g = blockIdx.x * 8 + w;
    const __half* x = g_vx + g * PART;
    float xv0 = __half2float(x[lane]);
    float xv1 = __half2float(x[32 + lane]);
    float acc = Bsh[lane];
#pragma unroll
    for (int f = 0; f < 32; f++)
        acc += __shfl_sync(0xffffffffu, xv0, f) * Ws[f * 32 + lane];
#pragma unroll
    for (int f = 0; f < 32; f++)
        acc += __shfl_sync(0xffffffffu, xv1, f) * Ws[(32 + f) * 32 + lane];
    int n = g >> 3, b = g & 7;
    out[(b * NN + n) * 32 + lane] = acc;
}

// ---------------- launch ----------------
extern "C" void kernel_launch(void* const* d_in, const int* in_sizes, int n_in,
                              void* d_out, int out_size) {
    (void)in_sizes; (void)n_in; (void)out_size;
    const float* ew = (const float*)d_in[0];
    const float* hs = (const float*)d_in[1];
    const float* go = (const float*)d_in[2];
    const float* Wz = (const float*)d_in[3];
    const float* bz = (const float*)d_in[4];
    const float* Wr = (const float*)d_in[5];
    const float* br = (const float*)d_in[6];
    const float* Wh = (const float*)d_in[7];
    const float* bh = (const float*)d_in[8];
    const float* pw = (const float*)d_in[9];
    const float* pb = (const float*)d_in[10];
    const int*   ei = (const int*)d_in[11];
    float* out = (float*)d_out;

    k_zero  <<<(NN + 255) / 256, 256>>>();
    k_degcnt<<<(EE + 255) / 256, 256>>>(ew, ei);
    k_scan  <<<2, 1024>>>();
    k_fill  <<<(EE + 255) / 256, 256>>>(ew, ei);
    k_init_x<<<(NB * HH + 255) / 256, 256>>>(go);
    k_load_h<<<(2 * NB * HH + 255) / 256, 256>>>(hs);
    k_build_wzr<<<(2 * 128 * 640 + 255) / 256, 256>>>(Wz, Wr);
    k_build_wh <<<(2 * 64 * 640 + 255) / 256, 256>>>(Wh);

    dim3 g2(NN, 2, 2), g1(NN, 1, 2);
    for (int l = 0; l < 2; l++) {
        k_prop5<<<g2, 256>>>(0, 1, l, 0, 1, 0, 2, 0, 0);   // slot1 = A_f s0; slot2 = A_r s0
        k_prop5<<<g2, 256>>>(0, 1, l, 1, 3, 2, 4, 1, 0);   // slot3/4 = 2 A(slot1/2) - s0

        k_gemm_zr<<<625, 256>>>(l, bz + l * HH, br + l * HH);

        k_prop5<<<g1, 256>>>(2, 2, l, 0, 1, 0, 2, 0, 0);
        k_prop5<<<g1, 256>>>(2, 2, l, 1, 3, 2, 4, 1, 0);

        k_gemm_h<<<625, 256>>>(l, bh + l * HH);            // -> new h in vx slot0
    }

    k_proj<<<NB / 8, 256>>>(pw, pb, out);
}

// round 12
// speedup vs baseline: 1.0628x; 1.0465x over previous
#include <cuda_runtime.h>
#include <cuda_fp16.h>

#define NN   10000
#define EE   160000
#define EEP  240000         // padded CSR capacity: EE + 8*NN
#define BB   8
#define HH   64
#define PART 320            // 5 slots * 64 features per (node,batch) row
#define NB   (NN*BB)        // 80000
#define VHL  (NB*PART)      // one vh layer

// ---------------- device scratch ----------------
__device__ float g_deg_out[NN];
__device__ float g_deg_in[NN];
__device__ int   g_cnt[2][NN];
__device__ int   g_off[2][NN+1];
__device__ int   g_cur[2][NN];
__device__ int   g_nbr[2][EEP];
__device__ float g_wgt[2][EEP];

__device__ __half g_vx[VHL];      // x-part slots: 0=x 1=A_f x 2=A_r x 3=cheb_f 4=cheb_r
__device__ __half g_vh[2*VHL];    // h-part slots, per layer
__device__ __half g_vr[VHL];      // (R*h)-part slots
__device__ float  g_z [NB*HH];    // Z gate (fp32)
__device__ __half g_WZR[2*128*640];  // fp16 weights, n-major [l][n][640] for Z|R gemm
__device__ __half g_WH [2*64*640];   // fp16 weights, n-major [l][n][640] for H gemm

// ---------------- helpers ----------------
struct __align__(8)  h2x2 { __half2 a, b; };
struct __align__(16) h2x4 { __half2 a, b, c, d; };

__device__ __forceinline__ float sigm(float x) { return 1.f / (1.f + __expf(-x)); }

__device__ __forceinline__ void mma_f16(float &c0, float &c1, float &c2, float &c3,
                                        unsigned a0, unsigned a1, unsigned a2, unsigned a3,
                                        unsigned b0, unsigned b1) {
    asm volatile(
        "mma.sync.aligned.m16n8k16.row.col.f32.f16.f16.f32 "
        "{%0,%1,%2,%3}, {%4,%5,%6,%7}, {%8,%9}, {%0,%1,%2,%3};"
        : "+f"(c0), "+f"(c1), "+f"(c2), "+f"(c3)
        : "r"(a0), "r"(a1), "r"(a2), "r"(a3), "r"(b0), "r"(b1));
}

__device__ __forceinline__ __half* partbuf(int id, int l) {
    return id == 0 ? g_vx : (id == 1 ? g_vh + l * VHL : g_vr);
}

// ---------------- setup ----------------
__global__ void k_zero() {
    int i = blockIdx.x * 256 + threadIdx.x;
    if (i < NN) {
        g_deg_out[i] = 0.f; g_deg_in[i] = 0.f;
        g_cnt[0][i] = 0;    g_cnt[1][i] = 0;
    }
}

__global__ void k_degcnt(const float* __restrict__ ew, const int* __restrict__ ei) {
    int e = blockIdx.x * 256 + threadIdx.x;
    if (e >= EE) return;
    int s = ei[e], d = ei[EE + e];
    float w = ew[e];
    atomicAdd(&g_deg_out[s], w);
    atomicAdd(&g_deg_in[d],  w);
    atomicAdd(&g_cnt[0][d], 1);
    atomicAdd(&g_cnt[1][s], 1);
}

// scan with counts padded up to multiples of 8
__global__ void k_scan() {   // grid=2, block=1024
    int d = blockIdx.x;
    __shared__ int sums[1024];
    int t = threadIdx.x;
    const int CH = 10;
    int base = t * CH;
    int s = 0;
    for (int i = 0; i < CH; i++) {
        int idx = base + i;
        if (idx < NN) s += (g_cnt[d][idx] + 7) & ~7;
    }
    sums[t] = s; __syncthreads();
    for (int off = 1; off < 1024; off <<= 1) {
        int v = (t >= off) ? sums[t - off] : 0;
        __syncthreads();
        sums[t] += v;
        __syncthreads();
    }
    int run = (t == 0) ? 0 : sums[t - 1];
    for (int i = 0; i < CH; i++) {
        int idx = base + i;
        if (idx < NN) {
            g_off[d][idx] = run; g_cur[d][idx] = run;
            run += (g_cnt[d][idx] + 7) & ~7;
        }
    }
    if (t == 1023) g_off[d][NN] = run;
}

__global__ void k_fill(const float* __restrict__ ew, const int* __restrict__ ei) {
    int e = blockIdx.x * 256 + threadIdx.x;
    if (e >= EE) return;
    int s = ei[e], d = ei[EE + e];
    float w = ew[e];
    float wo = g_deg_out[s]; float nout = w / (wo > 0.f ? wo : 1.f);
    float wi = g_deg_in[d];  float nin  = w / (wi > 0.f ? wi : 1.f);
    int p = atomicAdd(&g_cur[0][d], 1); g_nbr[0][p] = s; g_wgt[0][p] = nout;
    int q = atomicAdd(&g_cur[1][s], 1); g_nbr[1][q] = d; g_wgt[1][q] = nin;
}

// fill padding slots (up to 7 per node per dir) with nbr=0, wgt=0
__global__ void k_pad() {
    int i = blockIdx.x * 256 + threadIdx.x;
    if (i >= 2 * NN) return;
    int d = i >= NN ? 1 : 0;
    int n = i - d * NN;
    int s = g_cur[d][n], e = g_off[d][n + 1];
    for (int j = s; j < e; j++) { g_nbr[d][j] = 0; g_wgt[d][j] = 0.f; }
}

// go -> vx slot0; hs (both layers) -> vh slot0
__global__ void k_load_acts(const float* __restrict__ go, const float* __restrict__ hs) {
    int t = blockIdx.x * 256 + threadIdx.x;
    if (t >= 3 * NB * HH) return;
    int seg = t / (NB * HH);
    int tt = t - seg * (NB * HH);
    int f = tt & 63; int rest = tt >> 6;
    int n = rest % NN; int b = rest / NN;
    int row = (n * BB + b) * PART + f;
    if (seg == 0) g_vx[row] = __float2half_rn(go[tt]);
    else          g_vh[(seg - 1) * VHL + row] = __float2half_rn(hs[(seg - 1) * NB * HH + tt]);
}

// W layout [L,2,K,128,64]. Slots: 0:(dir0+dir1,k0) 1:(0,k1) 2:(1,k1) 3:(0,k2) 4:(1,k2)
__device__ __forceinline__ float wslot(const float* W, int l, int s, int wrow, int o) {
    if (s == 0) {
        return W[((((l*2+0)*3+0)*128 + wrow)*64) + o] +
               W[((((l*2+1)*3+0)*128 + wrow)*64) + o];
    }
    int dir = (s == 1 || s == 3) ? 0 : 1;
    int k   = (s <= 2) ? 1 : 2;
    return W[((((l*2+dir)*3+k)*128 + wrow)*64) + o];
}

// builds fp16 n-major: g_WZR[l][n][j], j in [0,640)
__global__ void k_build_wzr(const float* __restrict__ Wz, const float* __restrict__ Wr) {
    int idx = blockIdx.x * 256 + threadIdx.x;
    if (idx >= 2 * 128 * 640) return;
    int l = idx >= 128 * 640 ? 1 : 0;
    int li = idx - l * 128 * 640;
    int n = li / 640, j = li % 640;
    int p = j / 320, s = (j % 320) / 64, f = j & 63;
    int wrow = p * 64 + f;
    const float* W = (n < 64) ? Wz : Wr;
    g_WZR[l * 128 * 640 + n * 640 + j] = __float2half_rn(wslot(W, l, s, wrow, n & 63));
}

__global__ void k_build_wh(const float* __restrict__ Wh) {
    int idx = blockIdx.x * 256 + threadIdx.x;
    if (idx >= 2 * 64 * 640) return;
    int l = idx >= 64 * 640 ? 1 : 0;
    int li = idx - l * 64 * 640;
    int n = li / 640, j = li % 640;
    int p = j / 320, s = (j % 320) / 64, f = j & 63;
    g_WH[l * 64 * 640 + n * 640 + j] = __float2half_rn(wslot(Wh, l, s, p * 64 + f, n));
}

// ---------------- propagation v6: R7 geometry + padded CSR (no remainder) ----------------
// grid: (NN, nbuf, 2 dirs); block 128: warp = 2 batches, 16 lanes * 4 halves = 64 feats
__global__ void __launch_bounds__(128) k_prop6(int bufA, int bufB, int lvh,
                                               int s_in_f, int s_out_f,
                                               int s_in_r, int s_out_r,
                                               int cheb, int s_prev) {
    int dir = blockIdx.z;
    __half* buf = partbuf(blockIdx.y == 0 ? bufA : bufB, lvh);
    const int*   off = g_off[dir];
    const int*   nbr = g_nbr[dir];
    const float* wgt = g_wgt[dir];
    int s_in  = dir ? s_in_r  : s_in_f;
    int s_out = dir ? s_out_r : s_out_f;
    int n    = blockIdx.x;
    int w    = threadIdx.x >> 5;
    int lane = threadIdx.x & 31;
    int b    = w * 2 + (lane >> 4);
    int fo   = (lane & 15) * 4;        // half offset within 64
    int beg = off[n], end = off[n + 1];   // end-beg is a multiple of 8
    int inoff = s_in * 64 + fo;
    float4 acc = make_float4(0.f, 0.f, 0.f, 0.f);
    for (int j = beg; j < end; j += 8) {
#pragma unroll
        for (int u = 0; u < 8; u++) {
            int   m  = __ldg(&nbr[j + u]);
            float ww = __ldg(&wgt[j + u]);
            h2x2 v = *(const h2x2*)(buf + (m * BB + b) * PART + inoff);
            float2 f01 = __half22float2(v.a);
            float2 f23 = __half22float2(v.b);
            acc.x += ww * f01.x; acc.y += ww * f01.y;
            acc.z += ww * f23.x; acc.w += ww * f23.y;
        }
    }
    int orow = (n * BB + b) * PART;
    float4 res = acc;
    if (cheb) {
        h2x2 pv = *(const h2x2*)(buf + orow + s_prev * 64 + fo);
        float2 p01 = __half22float2(pv.a);
        float2 p23 = __half22float2(pv.b);
        res.x = 2.f * acc.x - p01.x; res.y = 2.f * acc.y - p01.y;
        res.z = 2.f * acc.z - p23.x; res.w = 2.f * acc.w - p23.y;
    }
    h2x2 o;
    o.a = __floats2half2_rn(res.x, res.y);
    o.b = __floats2half2_rn(res.z, res.w);
    *(h2x2*)(buf + orow + s_out * 64 + fo) = o;
}

// ---------------- fp16 tensor-core GEMMs ----------------
// Z|R: [80000 x 640] @ [640 x 128]; A row = (vx row | vh row), all fp16
// Block 256 = 8 warps, tile 128x128, warps 4x2 (32 rows x 64 cols each)
__global__ void __launch_bounds__(256) k_gemm_zr(int l,
                                                 const float* __restrict__ bz,
                                                 const float* __restrict__ br) {
    __shared__ __half As[128][40];   // row-major, padded (conflict-free quad reads)
    __shared__ __half Bs[128][40];   // n-major: Bs[n][k]
    const __half* W = g_WZR + l * 128 * 640;
    const __half* vh = g_vh + l * VHL;
    int tid = threadIdx.x;
    int wid = tid >> 5, lane = tid & 31;
    int warpM = wid & 3, warpN = wid >> 2;
    int g4 = lane >> 2, t4 = lane & 3;
    int rowBase = blockIdx.x * 128;

    float c[2][8][4];
#pragma unroll
    for (int mt = 0; mt < 2; mt++)
#pragma unroll
        for (int nt = 0; nt < 8; nt++)
#pragma unroll
            for (int i = 0; i < 4; i++) c[mt][nt][i] = 0.f;

    for (int kk = 0; kk < 20; kk++) {
        const __half* Asrc = (kk < 10) ? g_vx : vh;
        int soff = (kk < 10 ? kk : kk - 10) * 32;
#pragma unroll
        for (int t = 0; t < 2; t++) {           // A: 128x32 halves = 512 h2x4
            int id = tid + t * 256;
            int r = id >> 2, c8 = (id & 3) * 8;
            *(h2x4*)&As[r][c8] = *(const h2x4*)(Asrc + (rowBase + r) * PART + soff + c8);
        }
#pragma unroll
        for (int t = 0; t < 2; t++) {           // B: 128 n x 32 k halves = 512 h2x4
            int id = tid + t * 256;
            int n = id >> 2, c8 = (id & 3) * 8;
            *(h2x4*)&Bs[n][c8] = *(const h2x4*)(W + n * 640 + kk * 32 + c8);
        }
        __syncthreads();
#pragma unroll
        for (int kc = 0; kc < 2; kc++) {
            int k0 = kc * 16;
            int kA = k0 + 2 * t4;
            unsigned a[2][4];
#pragma unroll
            for (int mt = 0; mt < 2; mt++) {
                int rm = warpM * 32 + mt * 16;
                a[mt][0] = *(const unsigned*)&As[rm + g4][kA];
                a[mt][1] = *(const unsigned*)&As[rm + g4 + 8][kA];
                a[mt][2] = *(const unsigned*)&As[rm + g4][kA + 8];
                a[mt][3] = *(const unsigned*)&As[rm + g4 + 8][kA + 8];
            }
#pragma unroll
            for (int nt = 0; nt < 8; nt++) {
                int cn = warpN * 64 + nt * 8;
                unsigned b0 = *(const unsigned*)&Bs[cn + g4][kA];
                unsigned b1 = *(const unsigned*)&Bs[cn + g4][kA + 8];
#pragma unroll
                for (int mt = 0; mt < 2; mt++)
                    mma_f16(c[mt][nt][0], c[mt][nt][1], c[mt][nt][2], c[mt][nt][3],
                            a[mt][0], a[mt][1], a[mt][2], a[mt][3], b0, b1);
            }
        }
        __syncthreads();
    }

    // epilogue: warpN==0 -> Z gate; warpN==1 -> R gate * h
#pragma unroll
    for (int mt = 0; mt < 2; mt++) {
#pragma unroll
        for (int nt = 0; nt < 8; nt++) {
            int gr0 = rowBase + warpM * 32 + mt * 16 + g4;
            int cv  = nt * 8 + 2 * t4;
            if (warpN == 0) {
                float bz0 = __ldg(&bz[cv]), bz1 = __ldg(&bz[cv + 1]);
                g_z[gr0 * HH + cv]           = sigm(c[mt][nt][0] + bz0);
                g_z[gr0 * HH + cv + 1]       = sigm(c[mt][nt][1] + bz1);
                g_z[(gr0 + 8) * HH + cv]     = sigm(c[mt][nt][2] + bz0);
                g_z[(gr0 + 8) * HH + cv + 1] = sigm(c[mt][nt][3] + bz1);
            } else {
                float br0 = __ldg(&br[cv]), br1 = __ldg(&br[cv + 1]);
                float h00 = __half2float(vh[gr0 * PART + cv]);
                float h01 = __half2float(vh[gr0 * PART + cv + 1]);
                float h10 = __half2float(vh[(gr0 + 8) * PART + cv]);
                float h11 = __half2float(vh[(gr0 + 8) * PART + cv + 1]);
                g_vr[gr0 * PART + cv]           = __float2half_rn(sigm(c[mt][nt][0] + br0) * h00);
                g_vr[gr0 * PART + cv + 1]       = __float2half_rn(sigm(c[mt][nt][1] + br1) * h01);
                g_vr[(gr0 + 8) * PART + cv]     = __float2half_rn(sigm(c[mt][nt][2] + br0) * h10);
                g_vr[(gr0 + 8) * PART + cv + 1] = __float2half_rn(sigm(c[mt][nt][3] + br1) * h11);
            }
        }
    }
}

// H: [80000 x 640] @ [640 x 64]; A row = (vx row | vr row). GRU update -> vx slot0
// Block 256 = 8 warps, tile 128x64, each warp 16 rows x 64 cols
__global__ void __launch_bounds__(256) k_gemm_h(int l, const float* __restrict__ bh) {
    __shared__ __half As[128][40];
    __shared__ __half Bs[64][40];
    const __half* W = g_WH + l * 64 * 640;
    const __half* vh = g_vh + l * VHL;
    int tid = threadIdx.x;
    int wid = tid >> 5, lane = tid & 31;
    int g4 = lane >> 2, t4 = lane & 3;
    int rowBase = blockIdx.x * 128;

    float c[8][4];
#pragma unroll
    for (int nt = 0; nt < 8; nt++)
#pragma unroll
        for (int i = 0; i < 4; i++) c[nt][i] = 0.f;

    for (int kk = 0; kk < 20; kk++) {
        const __half* Asrc = (kk < 10) ? g_vx : g_vr;
        int soff = (kk < 10 ? kk : kk - 10) * 32;
#pragma unroll
        for (int t = 0; t < 2; t++) {           // A: 512 h2x4
            int id = tid + t * 256;
            int r = id >> 2, c8 = (id & 3) * 8;
            *(h2x4*)&As[r][c8] = *(const h2x4*)(Asrc + (rowBase + r) * PART + soff + c8);
        }
        {                                       // B: 64 n x 32 k = 256 h2x4
            int n = tid >> 2, c8 = (tid & 3) * 8;
            *(h2x4*)&Bs[n][c8] = *(const h2x4*)(W + n * 640 + kk * 32 + c8);
        }
        __syncthreads();
#pragma unroll
        for (int kc = 0; kc < 2; kc++) {
            int kA = kc * 16 + 2 * t4;
            int rm = wid * 16;
            unsigned a0 = *(const unsigned*)&As[rm + g4][kA];
            unsigned a1 = *(const unsigned*)&As[rm + g4 + 8][kA];
            unsigned a2 = *(const unsigned*)&As[rm + g4][kA + 8];
            unsigned a3 = *(const unsigned*)&As[rm + g4 + 8][kA + 8];
#pragma unroll
            for (int nt = 0; nt < 8; nt++) {
                unsigned b0 = *(const unsigned*)&Bs[nt * 8 + g4][kA];
                unsigned b1 = *(const unsigned*)&Bs[nt * 8 + g4][kA + 8];
                mma_f16(c[nt][0], c[nt][1], c[nt][2], c[nt][3], a0, a1, a2, a3, b0, b1);
            }
        }
        __syncthreads();
    }

    // epilogue: GRU update, write new h into vx slot0 (fp16)
#pragma unroll
    for (int nt = 0; nt < 8; nt++) {
        int gr0 = rowBase + wid * 16 + g4;
        int cv  = nt * 8 + 2 * t4;
        float bh0 = __ldg(&bh[cv]), bh1 = __ldg(&bh[cv + 1]);
#pragma unroll
        for (int half_i = 0; half_i < 2; half_i++) {
            int gr = gr0 + half_i * 8;
            float ht0 = tanhf(c[nt][half_i * 2 + 0] + bh0);
            float ht1 = tanhf(c[nt][half_i * 2 + 1] + bh1);
            float z0 = g_z[gr * HH + cv], z1 = g_z[gr * HH + cv + 1];
            float h0 = __half2float(vh[gr * PART + cv]);
            float h1 = __half2float(vh[gr * PART + cv + 1]);
            g_vx[gr * PART + cv]     = __float2half_rn(z0 * h0 + (1.f - z0) * ht0);
            g_vx[gr * PART + cv + 1] = __float2half_rn(z1 * h1 + (1.f - z1) * ht1);
        }
    }
}

// ---------------- projection ----------------
__global__ void __launch_bounds__(256) k_proj(const float* __restrict__ pw,
                                              const float* __restrict__ pb,
                                              float* __restrict__ out) {
    __shared__ float Ws[64 * 32];
    __shared__ float Bsh[32];
    int tid = threadIdx.x;
    for (int i = tid; i < 64 * 32; i += 256) Ws[i] = pw[i];
    if (tid < 32) Bsh[tid] = pb[tid];
    __syncthreads();
    int w = tid >> 5, lane = tid & 31;
    int g = blockIdx.x * 8 + w;
    const __half* x = g_vx + g * PART;
    float xv0 = __half2float(x[lane]);
    float xv1 = __half2float(x[32 + lane]);
    float acc = Bsh[lane];
#pragma unroll
    for (int f = 0; f < 32; f++)
        acc += __shfl_sync(0xffffffffu, xv0, f) * Ws[f * 32 + lane];
#pragma unroll
    for (int f = 0; f < 32; f++)
        acc += __shfl_sync(0xffffffffu, xv1, f) * Ws[(32 + f) * 32 + lane];
    int n = g >> 3, b = g & 7;
    out[(b * NN + n) * 32 + lane] = acc;
}

// ---------------- launch ----------------
extern "C" void kernel_launch(void* const* d_in, const int* in_sizes, int n_in,
                              void* d_out, int out_size) {
    (void)in_sizes; (void)n_in; (void)out_size;
    const float* ew = (const float*)d_in[0];
    const float* hs = (const float*)d_in[1];
    const float* go = (const float*)d_in[2];
    const float* Wz = (const float*)d_in[3];
    const float* bz = (const float*)d_in[4];
    const float* Wr = (const float*)d_in[5];
    const float* br = (const float*)d_in[6];
    const float* Wh = (const float*)d_in[7];
    const float* bh = (const float*)d_in[8];
    const float* pw = (const float*)d_in[9];
    const float* pb = (const float*)d_in[10];
    const int*   ei = (const int*)d_in[11];
    float* out = (float*)d_out;

    k_zero  <<<(NN + 255) / 256, 256>>>();
    k_degcnt<<<(EE + 255) / 256, 256>>>(ew, ei);
    k_scan  <<<2, 1024>>>();
    k_fill  <<<(EE + 255) / 256, 256>>>(ew, ei);
    k_pad   <<<(2 * NN + 255) / 256, 256>>>();
    k_load_acts<<<(3 * NB * HH + 255) / 256, 256>>>(go, hs);
    k_build_wzr<<<(2 * 128 * 640 + 255) / 256, 256>>>(Wz, Wr);
    k_build_wh <<<(2 * 64 * 640 + 255) / 256, 256>>>(Wh);

    dim3 g2(NN, 2, 2), g1(NN, 1, 2);
    for (int l = 0; l < 2; l++) {
        k_prop6<<<g2, 128>>>(0, 1, l, 0, 1, 0, 2, 0, 0);   // slot1 = A_f s0; slot2 = A_r s0
        k_prop6<<<g2, 128>>>(0, 1, l, 1, 3, 2, 4, 1, 0);   // slot3/4 = 2 A(slot1/2) - s0

        k_gemm_zr<<<625, 256>>>(l, bz + l * HH, br + l * HH);

        k_prop6<<<g1, 128>>>(2, 2, l, 0, 1, 0, 2, 0, 0);
        k_prop6<<<g1, 128>>>(2, 2, l, 1, 3, 2, 4, 1, 0);

        k_gemm_h<<<625, 256>>>(l, bh + l * HH);            // -> new h in vx slot0
    }

    k_proj<<<NB / 8, 256>>>(pw, pb, out);
}